// round 1
// baseline (speedup 1.0000x reference)
#include <cuda_runtime.h>

#define HID 128
#define E_ 262144
#define N_ 32768
#define GEO_ 13
#define K0PAD 400
#define ROWS_MAX (E_ + 512)
#define GRID_G (ROWS_MAX / 128)

typedef unsigned long long u64;

// ---------------- scratch (device globals; no allocation) ----------------
__device__ float g_hA[(size_t)ROWS_MAX * HID];
__device__ float g_hB[(size_t)ROWS_MAX * HID];
__device__ float g_W0T[4 * K0PAD * HID];          // [r][k(padded 400)][n]
__device__ float g_WT[4 * 3 * HID * HID];         // [r][l][k][n]
__device__ int   g_perm[ROWS_MAX];
__device__ int   g_route[E_];
__device__ int   g_cnt[4];
__device__ int   g_cur[4];
__device__ int   g_bnd[5];
__device__ float g_cntf[4];
__device__ float g_stats[4][4][HID][2];           // [layer][route][chan][sum,sumsq]
__device__ float g_st[4][4][HID][2];              // [layer][route][chan][scale,shift]

// ---------------- packed f32x2 helpers ----------------
__device__ __forceinline__ u64 pack2(float lo, float hi){
  u64 r; asm("mov.b64 %0, {%1,%2};" : "=l"(r) : "f"(lo), "f"(hi)); return r;
}
__device__ __forceinline__ void unpack2(u64 v, float& lo, float& hi){
  asm("mov.b64 {%0,%1}, %2;" : "=f"(lo), "=f"(hi) : "l"(v));
}
__device__ __forceinline__ void fma2(u64& acc, u64 a, u64 b){
  asm("fma.rn.f32x2 %0, %1, %2, %3;" : "=l"(acc) : "l"(a), "l"(b), "l"(acc));
}

// ---------------- init: zero out/stats/counters, fill perm with -1 ----------------
__global__ void k_init(float* __restrict__ out){
  int idx = blockIdx.x * 256 + threadIdx.x;
  if (idx < N_ * HID) out[idx] = 0.f;
  if (idx < ROWS_MAX) g_perm[idx] = -1;
  if (idx < 4 * 4 * HID * 2) ((float*)g_stats)[idx] = 0.f;
  if (idx < 4) { g_cnt[idx] = 0; g_cur[idx] = 0; }
}

// ---------------- transpose weights into [k][n] layout (K-padded for W0) ----------------
__global__ void k_prep(const float* __restrict__ W0, const float* __restrict__ W){
  int idx = blockIdx.x * 256 + threadIdx.x;
  const int n0 = 4 * K0PAD * HID;           // 204800
  const int n1 = 4 * 3 * HID * HID;         // 196608
  if (idx < n0) {
    int r   = idx / (K0PAD * HID);
    int rem = idx - r * (K0PAD * HID);
    int k   = rem / HID;
    int n   = rem - k * HID;
    g_W0T[idx] = (k < 397) ? W0[(r * HID + n) * 397 + k] : 0.f;
  } else if (idx < n0 + n1) {
    int off = idx - n0;
    int rl  = off / (HID * HID);            // r*3 + l
    int rem = off - rl * (HID * HID);
    int k   = rem / HID;
    int n   = rem - k * HID;
    g_WT[off] = W[(rl * HID + n) * HID + k];
  }
}

// ---------------- route + count (warp-aggregated atomics) ----------------
__global__ void k_route(const int* __restrict__ eij, const int* __restrict__ ejk,
                        const int* __restrict__ nei_ptr){
  int e = blockIdx.x * 256 + threadIdx.x;
  if (e >= E_) return;
  int nei = nei_ptr[0];
  int r = ((eij[e] < nei) ? 0 : 2) | ((ejk[e] < nei) ? 0 : 1);
  g_route[e] = r;
  int lane = threadIdx.x & 31;
  #pragma unroll
  for (int rr = 0; rr < 4; rr++){
    unsigned m = __ballot_sync(0xFFFFFFFFu, r == rr);
    if (r == rr && lane == (__ffs(m) - 1)) atomicAdd(&g_cnt[rr], __popc(m));
  }
}

// ---------------- padded segment offsets ----------------
__global__ void k_offsets(){
  if (threadIdx.x == 0){
    int b = 0;
    #pragma unroll
    for (int r = 0; r < 4; r++){
      g_bnd[r] = b;
      int c = g_cnt[r];
      b += ((c + 127) / 128) * 128;
      g_cntf[r] = (c > 0) ? (float)c : 1.0f;
    }
    g_bnd[4] = b;
  }
}

// ---------------- build permutation (route-grouped, pads = -1 at tail) ----------------
__global__ void k_perm(){
  int e = blockIdx.x * 256 + threadIdx.x;
  if (e >= E_) return;
  int r = g_route[e];
  int lane = threadIdx.x & 31;
  #pragma unroll
  for (int rr = 0; rr < 4; rr++){
    unsigned m = __ballot_sync(0xFFFFFFFFu, r == rr);
    if (r == rr){
      int leader = __ffs(m) - 1;
      int base = 0;
      if (lane == leader) base = atomicAdd(&g_cur[rr], __popc(m));
      base = __shfl_sync(m, base, leader);
      unsigned lt = (lane == 0) ? 0u : (0xFFFFFFFFu >> (32 - lane));
      int pos = g_bnd[rr] + base + __popc(m & lt);
      g_perm[pos] = e;
    }
  }
}

// ---------------- GEMM layer 0: gather x = [nf[i],nf[j],nf[k],geo], h = x*W0[r]^T + b0 ----
__global__ __launch_bounds__(256, 2)
void k_gemm0(const float* __restrict__ nf, const float* __restrict__ geo,
             const int* __restrict__ ei, const float* __restrict__ b0){
  __shared__ float tiles[2048];               // As[8][128] | Bs[8][128]; reused as red[16][128]
  __shared__ int sE[128], sI[128], sJ[128], sK[128];
  float* As = tiles;
  float* Bs = tiles + 1024;

  int m0 = blockIdx.x << 7;
  if (m0 >= g_bnd[4]) return;
  int r = 0;
  #pragma unroll
  for (int q = 1; q < 4; q++) if (m0 >= g_bnd[q]) r = q;

  int tid = threadIdx.x;
  if (tid < 128){
    int e = g_perm[m0 + tid];
    sE[tid] = e;
    int i = 0, j = 0, kk = 0;
    if (e >= 0){ i = ei[e]; j = ei[E_ + e]; kk = ei[2 * E_ + e]; }
    sI[tid] = i; sJ[tid] = j; sK[tid] = kk;
  }
  __syncthreads();

  int tx = tid & 15, ty = tid >> 4;
  int arow  = tid >> 1;
  int ahalf = (tid & 1) << 2;
  int bk = tid >> 5;
  int bn = (tid & 31) << 2;
  const float* W0r = g_W0T + r * K0PAD * HID;

  u64 acc[4][8];
  #pragma unroll
  for (int p = 0; p < 4; p++)
    #pragma unroll
    for (int j = 0; j < 8; j++) acc[p][j] = 0ull;

  int eA = sE[arow];
  int ia = sI[arow], ja = sJ[arow], ka = sK[arow];

  for (int kt = 0; kt < 50; kt++){
    int k0 = kt << 3;
    float4 bv = *(const float4*)&W0r[(k0 + bk) * HID + bn];
    float4 av = make_float4(0.f, 0.f, 0.f, 0.f);
    int kg = k0 + ahalf;
    if (eA >= 0){
      if (kg < 128)       av = *(const float4*)&nf[ia * HID + kg];
      else if (kg < 256)  av = *(const float4*)&nf[ja * HID + kg - 128];
      else if (kg < 384)  av = *(const float4*)&nf[ka * HID + kg - 256];
      else {
        int g0 = kg - 384;
        const float* gp = geo + eA * GEO_;
        av.x = (g0 + 0 < GEO_) ? gp[g0 + 0] : 0.f;
        av.y = (g0 + 1 < GEO_) ? gp[g0 + 1] : 0.f;
        av.z = (g0 + 2 < GEO_) ? gp[g0 + 2] : 0.f;
        av.w = (g0 + 3 < GEO_) ? gp[g0 + 3] : 0.f;
      }
    }
    __syncthreads();
    *(float4*)&Bs[bk * HID + bn] = bv;
    As[(ahalf + 0) * 128 + arow] = av.x;
    As[(ahalf + 1) * 128 + arow] = av.y;
    As[(ahalf + 2) * 128 + arow] = av.z;
    As[(ahalf + 3) * 128 + arow] = av.w;
    __syncthreads();
    #pragma unroll
    for (int kk = 0; kk < 8; kk++){
      const float* ar = &As[kk * 128 + (ty << 3)];
      u64 a2[4];
      #pragma unroll
      for (int p = 0; p < 4; p++) a2[p] = *(const u64*)&ar[p * 2];
      float4 bv0 = *(const float4*)&Bs[kk * 128 + (tx << 3)];
      float4 bv1 = *(const float4*)&Bs[kk * 128 + (tx << 3) + 4];
      float bf[8] = {bv0.x, bv0.y, bv0.z, bv0.w, bv1.x, bv1.y, bv1.z, bv1.w};
      #pragma unroll
      for (int j = 0; j < 8; j++){
        u64 bd = pack2(bf[j], bf[j]);
        #pragma unroll
        for (int p = 0; p < 4; p++) fma2(acc[p][j], a2[p], bd);
      }
    }
  }

  // -------- epilogue: bias, write h, per-channel stats --------
  const float* bias = b0 + r * HID;
  float bcol[8];
  #pragma unroll
  for (int j = 0; j < 8; j++) bcol[j] = bias[(tx << 3) + j];

  float psum[8], psq[8];
  #pragma unroll
  for (int j = 0; j < 8; j++){ psum[j] = 0.f; psq[j] = 0.f; }

  #pragma unroll
  for (int p = 0; p < 4; p++){
    float c0[8], c1[8];
    #pragma unroll
    for (int j = 0; j < 8; j++){
      float lo, hi; unpack2(acc[p][j], lo, hi);
      c0[j] = lo + bcol[j]; c1[j] = hi + bcol[j];
    }
    int lr0 = (ty << 3) + (p << 1);
    int row0 = m0 + lr0;
    float4 w;
    w.x = c0[0]; w.y = c0[1]; w.z = c0[2]; w.w = c0[3];
    *(float4*)&g_hA[row0 * HID + (tx << 3)] = w;
    w.x = c0[4]; w.y = c0[5]; w.z = c0[6]; w.w = c0[7];
    *(float4*)&g_hA[row0 * HID + (tx << 3) + 4] = w;
    w.x = c1[0]; w.y = c1[1]; w.z = c1[2]; w.w = c1[3];
    *(float4*)&g_hA[(row0 + 1) * HID + (tx << 3)] = w;
    w.x = c1[4]; w.y = c1[5]; w.z = c1[6]; w.w = c1[7];
    *(float4*)&g_hA[(row0 + 1) * HID + (tx << 3) + 4] = w;
    bool v0 = sE[lr0] >= 0, v1 = sE[lr0 + 1] >= 0;
    #pragma unroll
    for (int j = 0; j < 8; j++){
      if (v0){ psum[j] += c0[j]; psq[j] += c0[j] * c0[j]; }
      if (v1){ psum[j] += c1[j]; psq[j] += c1[j] * c1[j]; }
    }
  }

  __syncthreads();
  float* red = tiles;
  #pragma unroll
  for (int j = 0; j < 8; j++) red[ty * 128 + (tx << 3) + j] = psum[j];
  __syncthreads();
  if (tid < 128){
    float s = 0.f;
    #pragma unroll
    for (int t = 0; t < 16; t++) s += red[t * 128 + tid];
    atomicAdd(&g_stats[0][r][tid][0], s);
  }
  __syncthreads();
  #pragma unroll
  for (int j = 0; j < 8; j++) red[ty * 128 + (tx << 3) + j] = psq[j];
  __syncthreads();
  if (tid < 128){
    float s = 0.f;
    #pragma unroll
    for (int t = 0; t < 16; t++) s += red[t * 128 + tid];
    atomicAdd(&g_stats[0][r][tid][1], s);
  }
}

// ---------------- finalize BN stats -> scale/shift ----------------
__global__ void k_finalize(int layer, const float* __restrict__ gamma,
                           const float* __restrict__ beta){
  int t = threadIdx.x + blockIdx.x * blockDim.x;
  if (t >= 512) return;
  int r = t >> 7, c = t & 127;
  float cnt  = g_cntf[r];
  float sum  = g_stats[layer][r][c][0];
  float sq   = g_stats[layer][r][c][1];
  float mean = sum / cnt;
  float var  = fmaxf(sq / cnt - mean * mean, 0.f);
  float inv  = rsqrtf(var + 1e-5f);
  float g    = gamma[(r * 4 + layer) * HID + c];
  float bt   = beta[(r * 4 + layer) * HID + c];
  float s    = g * inv;
  g_st[layer][r][c][0] = s;
  g_st[layer][r][c][1] = bt - mean * s;
}

// ---------------- GEMM layers 1..3: A = relu(BN(h_prev)) on the fly ----------------
template<int LI>
__global__ __launch_bounds__(256, 2)
void k_gemml(const float* __restrict__ bArr){
  const float* hin  = (LI & 1) ? g_hA : g_hB;
  float*       hout = (LI & 1) ? g_hB : g_hA;

  __shared__ float tiles[2048];
  __shared__ float ssc[HID], ssh[HID];
  float* As = tiles;
  float* Bs = tiles + 1024;

  int m0 = blockIdx.x << 7;
  if (m0 >= g_bnd[4]) return;
  int r = 0;
  #pragma unroll
  for (int q = 1; q < 4; q++) if (m0 >= g_bnd[q]) r = q;

  int tid = threadIdx.x;
  if (tid < HID){
    ssc[tid] = g_st[LI - 1][r][tid][0];
    ssh[tid] = g_st[LI - 1][r][tid][1];
  }
  __syncthreads();

  int tx = tid & 15, ty = tid >> 4;
  int arow  = tid >> 1;
  int ahalf = (tid & 1) << 2;
  int bk = tid >> 5;
  int bn = (tid & 31) << 2;
  const float* Wr = g_WT + (r * 3 + (LI - 1)) * HID * HID;
  int vlim = g_bnd[r] + g_cnt[r];

  u64 acc[4][8];
  #pragma unroll
  for (int p = 0; p < 4; p++)
    #pragma unroll
    for (int j = 0; j < 8; j++) acc[p][j] = 0ull;

  for (int kt = 0; kt < 16; kt++){
    int k0 = kt << 3;
    float4 bv = *(const float4*)&Wr[(k0 + bk) * HID + bn];
    int kg = k0 + ahalf;
    float4 hv = *(const float4*)&hin[(m0 + arow) * HID + kg];
    float4 av;
    av.x = fmaxf(fmaf(hv.x, ssc[kg + 0], ssh[kg + 0]), 0.f);
    av.y = fmaxf(fmaf(hv.y, ssc[kg + 1], ssh[kg + 1]), 0.f);
    av.z = fmaxf(fmaf(hv.z, ssc[kg + 2], ssh[kg + 2]), 0.f);
    av.w = fmaxf(fmaf(hv.w, ssc[kg + 3], ssh[kg + 3]), 0.f);
    __syncthreads();
    *(float4*)&Bs[bk * HID + bn] = bv;
    As[(ahalf + 0) * 128 + arow] = av.x;
    As[(ahalf + 1) * 128 + arow] = av.y;
    As[(ahalf + 2) * 128 + arow] = av.z;
    As[(ahalf + 3) * 128 + arow] = av.w;
    __syncthreads();
    #pragma unroll
    for (int kk = 0; kk < 8; kk++){
      const float* ar = &As[kk * 128 + (ty << 3)];
      u64 a2[4];
      #pragma unroll
      for (int p = 0; p < 4; p++) a2[p] = *(const u64*)&ar[p * 2];
      float4 bv0 = *(const float4*)&Bs[kk * 128 + (tx << 3)];
      float4 bv1 = *(const float4*)&Bs[kk * 128 + (tx << 3) + 4];
      float bf[8] = {bv0.x, bv0.y, bv0.z, bv0.w, bv1.x, bv1.y, bv1.z, bv1.w};
      #pragma unroll
      for (int j = 0; j < 8; j++){
        u64 bd = pack2(bf[j], bf[j]);
        #pragma unroll
        for (int p = 0; p < 4; p++) fma2(acc[p][j], a2[p], bd);
      }
    }
  }

  const float* bias = bArr + (r * 3 + (LI - 1)) * HID;
  float bcol[8];
  #pragma unroll
  for (int j = 0; j < 8; j++) bcol[j] = bias[(tx << 3) + j];

  float psum[8], psq[8];
  #pragma unroll
  for (int j = 0; j < 8; j++){ psum[j] = 0.f; psq[j] = 0.f; }

  #pragma unroll
  for (int p = 0; p < 4; p++){
    float c0[8], c1[8];
    #pragma unroll
    for (int j = 0; j < 8; j++){
      float lo, hi; unpack2(acc[p][j], lo, hi);
      c0[j] = lo + bcol[j]; c1[j] = hi + bcol[j];
    }
    int lr0 = (ty << 3) + (p << 1);
    int row0 = m0 + lr0;
    float4 w;
    w.x = c0[0]; w.y = c0[1]; w.z = c0[2]; w.w = c0[3];
    *(float4*)&hout[row0 * HID + (tx << 3)] = w;
    w.x = c0[4]; w.y = c0[5]; w.z = c0[6]; w.w = c0[7];
    *(float4*)&hout[row0 * HID + (tx << 3) + 4] = w;
    w.x = c1[0]; w.y = c1[1]; w.z = c1[2]; w.w = c1[3];
    *(float4*)&hout[(row0 + 1) * HID + (tx << 3)] = w;
    w.x = c1[4]; w.y = c1[5]; w.z = c1[6]; w.w = c1[7];
    *(float4*)&hout[(row0 + 1) * HID + (tx << 3) + 4] = w;
    bool v0 = (row0 < vlim), v1 = (row0 + 1 < vlim);
    #pragma unroll
    for (int j = 0; j < 8; j++){
      if (v0){ psum[j] += c0[j]; psq[j] += c0[j] * c0[j]; }
      if (v1){ psum[j] += c1[j]; psq[j] += c1[j] * c1[j]; }
    }
  }

  __syncthreads();
  float* red = tiles;
  #pragma unroll
  for (int j = 0; j < 8; j++) red[ty * 128 + (tx << 3) + j] = psum[j];
  __syncthreads();
  if (tid < 128){
    float s = 0.f;
    #pragma unroll
    for (int t = 0; t < 16; t++) s += red[t * 128 + tid];
    atomicAdd(&g_stats[LI][r][tid][0], s);
  }
  __syncthreads();
  #pragma unroll
  for (int j = 0; j < 8; j++) red[ty * 128 + (tx << 3) + j] = psq[j];
  __syncthreads();
  if (tid < 128){
    float s = 0.f;
    #pragma unroll
    for (int t = 0; t < 16; t++) s += red[t * 128 + tid];
    atomicAdd(&g_stats[LI][r][tid][1], s);
  }
}

// ---------------- final: BN3 + relu (leaky is identity on relu output) * att, scatter ----
__global__ void k_final(const int* __restrict__ ei, const float* __restrict__ att,
                        float* __restrict__ out){
  int t = blockIdx.x * 256 + threadIdx.x;
  int row = t >> 5;
  if (row >= g_bnd[4]) return;
  int e = g_perm[row];
  if (e < 0) return;
  int r = 0;
  #pragma unroll
  for (int q = 1; q < 4; q++) if (row >= g_bnd[q]) r = q;
  int c0 = (t & 31) << 2;
  float a = att[r];
  int i = ei[e];
  float4 h = *(const float4*)&g_hB[row * HID + c0];
  float v0 = fmaxf(fmaf(h.x, g_st[3][r][c0 + 0][0], g_st[3][r][c0 + 0][1]), 0.f) * a;
  float v1 = fmaxf(fmaf(h.y, g_st[3][r][c0 + 1][0], g_st[3][r][c0 + 1][1]), 0.f) * a;
  float v2 = fmaxf(fmaf(h.z, g_st[3][r][c0 + 2][0], g_st[3][r][c0 + 2][1]), 0.f) * a;
  float v3 = fmaxf(fmaf(h.w, g_st[3][r][c0 + 3][0], g_st[3][r][c0 + 3][1]), 0.f) * a;
  atomicAdd(&out[i * HID + c0 + 0], v0);
  atomicAdd(&out[i * HID + c0 + 1], v1);
  atomicAdd(&out[i * HID + c0 + 2], v2);
  atomicAdd(&out[i * HID + c0 + 3], v3);
}

// ---------------- launch ----------------
extern "C" void kernel_launch(void* const* d_in, const int* in_sizes, int n_in,
                              void* d_out, int out_size){
  const float* nf    = (const float*)d_in[0];
  const float* geo   = (const float*)d_in[1];
  const int*   ei    = (const int*)d_in[2];
  const int*   eij   = (const int*)d_in[3];
  const int*   ejk   = (const int*)d_in[4];
  const int*   nei   = (const int*)d_in[5];
  const float* att   = (const float*)d_in[6];
  const float* W0    = (const float*)d_in[7];
  const float* b0    = (const float*)d_in[8];
  const float* W     = (const float*)d_in[9];
  const float* b     = (const float*)d_in[10];
  const float* gamma = (const float*)d_in[11];
  const float* beta  = (const float*)d_in[12];
  float* out = (float*)d_out;

  k_init<<<(N_ * HID) / 256, 256>>>(out);
  k_prep<<<(4 * K0PAD * HID + 4 * 3 * HID * HID + 255) / 256, 256>>>(W0, W);
  k_route<<<E_ / 256, 256>>>(eij, ejk, nei);
  k_offsets<<<1, 32>>>();
  k_perm<<<E_ / 256, 256>>>();

  k_gemm0<<<GRID_G, 256>>>(nf, geo, ei, b0);
  k_finalize<<<1, 512>>>(0, gamma, beta);
  k_gemml<1><<<GRID_G, 256>>>(b);
  k_finalize<<<1, 512>>>(1, gamma, beta);
  k_gemml<2><<<GRID_G, 256>>>(b);
  k_finalize<<<1, 512>>>(2, gamma, beta);
  k_gemml<3><<<GRID_G, 256>>>(b);
  k_finalize<<<1, 512>>>(3, gamma, beta);

  k_final<<<(ROWS_MAX * 32) / 256, 256>>>(ei, att, out);
}